// round 2
// baseline (speedup 1.0000x reference)
#include <cuda_runtime.h>
#include <math.h>

#define NP 100000
#define NA 100000
#define DIN 256
#define DOUT 128
#define NE 1600000
#define SLOPE 0.2f
#define CAP 96

// ---------------- scratch (static device globals; allocation-free) ----------
__device__ float g_Wh_P[NP * DOUT];
__device__ float g_Wh_A[NA * DOUT];
__device__ float g_Wh_p2p[NP * DOUT];
__device__ float g_Wh_p2a[NP * DOUT];
__device__ float g_Wh_a2p[NA * DOUT];
__device__ float g_Wh_a2a[NA * DOUT];
__device__ float g_recv_p2p[NP * DOUT];
__device__ float g_recv_a2p[NP * DOUT];
__device__ float g_recv_p2a[NA * DOUT];
__device__ float g_recv_a2a[NA * DOUT];
__device__ float g_s_p2p_src[NP];
__device__ float g_s_p2p_dst[NP];
__device__ float g_s_p2a_src[NP];
__device__ float g_s_p2a_dst[NA];
__device__ float g_s_a2p_src[NA];
__device__ float g_s_a2p_dst[NP];
__device__ float g_s_a2a_src[NA];
__device__ float g_s_a2a_dst[NA];
__device__ int   g_bsrc[NP * CAP];   // reused sequentially per edge type
__device__ float g_be[NP * CAP];
__device__ int   g_cnt[NP];

// ---------------- fused 3-way GEMM: out_w = feat @ W_w + b_w ----------------
// Tile: BM=64 rows x BN=128 cols, all 3 weight matrices at once so feat is
// read from HBM exactly once. Inner loop uses packed fma.rn.f32x2 (FFMA2).
#define BM 64
#define BN 128
#define BK 16
#define APAD 68   // padded As row length (16B-aligned, breaks store conflicts)

__global__ __launch_bounds__(256, 2)
void gemm3_kernel(const float* __restrict__ feat, int n,
                  const float* __restrict__ W0, const float* __restrict__ W1,
                  const float* __restrict__ W2,
                  const float* __restrict__ b0, const float* __restrict__ b1,
                  const float* __restrict__ b2,
                  float* __restrict__ o0, float* __restrict__ o1,
                  float* __restrict__ o2)
{
    __shared__ float As[BK][APAD];        // transposed: As[k][row]
    __shared__ float Bs[3][BK][BN];

    const int tid  = threadIdx.x;
    const int tx   = tid & 15;            // col group (8 cols each)
    const int ty   = tid >> 4;            // row group (4 rows each)
    const int row0 = blockIdx.x * BM;

    const float* Ws[3] = {W0, W1, W2};

    unsigned long long acc[3][4][4];      // [w][row][colpair], f32x2 packed
#pragma unroll
    for (int w = 0; w < 3; w++)
#pragma unroll
        for (int i = 0; i < 4; i++)
#pragma unroll
            for (int j = 0; j < 4; j++) acc[w][i][j] = 0ull;

    const int ar  = tid >> 2;             // 0..63 : row for A load
    const int akq = tid & 3;              // 0..3  : k-quad for A load
    const int bc4 = tid & 31;             // 0..31 : col/4 for B load
    const int bkr = tid >> 5;             // 0..7  : k row for B load

    for (int kc = 0; kc < DIN; kc += BK) {
        // load A tile (64 rows x 16 k), store transposed
        {
            float4 v = make_float4(0.f, 0.f, 0.f, 0.f);
            int grow = row0 + ar;
            if (grow < n)
                v = *(const float4*)(feat + (long)grow * DIN + kc + akq * 4);
            As[akq * 4 + 0][ar] = v.x;
            As[akq * 4 + 1][ar] = v.y;
            As[akq * 4 + 2][ar] = v.z;
            As[akq * 4 + 3][ar] = v.w;
        }
        // load B tiles (16 x 128) for all 3 weights
#pragma unroll
        for (int w = 0; w < 3; w++) {
#pragma unroll
            for (int p = 0; p < 2; p++) {
                int kk = bkr + p * 8;
                *(float4*)&Bs[w][kk][bc4 * 4] =
                    *(const float4*)(Ws[w] + (long)(kc + kk) * DOUT + bc4 * 4);
            }
        }
        __syncthreads();

#pragma unroll
        for (int k = 0; k < BK; k++) {
            float4 a = *(const float4*)&As[k][ty * 4];
            unsigned long long a2[4];
            asm("mov.b64 %0,{%1,%1};" : "=l"(a2[0]) : "f"(a.x));
            asm("mov.b64 %0,{%1,%1};" : "=l"(a2[1]) : "f"(a.y));
            asm("mov.b64 %0,{%1,%1};" : "=l"(a2[2]) : "f"(a.z));
            asm("mov.b64 %0,{%1,%1};" : "=l"(a2[3]) : "f"(a.w));
#pragma unroll
            for (int w = 0; w < 3; w++) {
                ulonglong2 bA = *(const ulonglong2*)&Bs[w][k][tx * 8];
                ulonglong2 bB = *(const ulonglong2*)&Bs[w][k][tx * 8 + 4];
                unsigned long long bp[4] = {bA.x, bA.y, bB.x, bB.y};
#pragma unroll
                for (int i = 0; i < 4; i++)
#pragma unroll
                    for (int j = 0; j < 4; j++)
                        asm("fma.rn.f32x2 %0, %1, %2, %0;"
                            : "+l"(acc[w][i][j]) : "l"(a2[i]), "l"(bp[j]));
            }
        }
        __syncthreads();
    }

    // epilogue: unpack, add bias, store
    float* Os[3]       = {o0, o1, o2};
    const float* Bv[3] = {b0, b1, b2};
#pragma unroll
    for (int w = 0; w < 3; w++) {
        float bias[8];
#pragma unroll
        for (int j = 0; j < 8; j++) bias[j] = Bv[w][tx * 8 + j];
#pragma unroll
        for (int i = 0; i < 4; i++) {
            int grow = row0 + ty * 4 + i;
            if (grow < n) {
                float ov[8];
#pragma unroll
                for (int j = 0; j < 4; j++) {
                    float lo, hi;
                    asm("mov.b64 {%0,%1}, %2;" : "=f"(lo), "=f"(hi)
                        : "l"(acc[w][i][j]));
                    ov[2 * j]     = lo + bias[2 * j];
                    ov[2 * j + 1] = hi + bias[2 * j + 1];
                }
                float* op = Os[w] + (long)grow * DOUT + tx * 8;
                *(float4*)(op)     = make_float4(ov[0], ov[1], ov[2], ov[3]);
                *(float4*)(op + 4) = make_float4(ov[4], ov[5], ov[6], ov[7]);
            }
        }
    }
}

// ---------------- attention score dots: s = Wh . a_half ---------------------
// One warp per node; computes 4 score arrays reading 3 Wh matrices.
__global__ void s_kernel(const float* __restrict__ WhD,
                         const float* __restrict__ Wm1,
                         const float* __restrict__ Wm2,
                         const float* __restrict__ aD1,
                         const float* __restrict__ aD2,
                         const float* __restrict__ aS1,
                         const float* __restrict__ aS2,
                         float* __restrict__ sD1, float* __restrict__ sD2,
                         float* __restrict__ sS1, float* __restrict__ sS2,
                         int n)
{
    int warp = (blockIdx.x * blockDim.x + threadIdx.x) >> 5;
    int lane = threadIdx.x & 31;
    if (warp >= n) return;

    float4 a1 = *(const float4*)(aD1 + lane * 4);
    float4 a2 = *(const float4*)(aD2 + lane * 4);
    float4 s1 = *(const float4*)(aS1 + lane * 4);
    float4 s2 = *(const float4*)(aS2 + lane * 4);

    float4 wd = *(const float4*)(WhD + (long)warp * DOUT + lane * 4);
    float4 m1 = *(const float4*)(Wm1 + (long)warp * DOUT + lane * 4);
    float4 m2 = *(const float4*)(Wm2 + (long)warp * DOUT + lane * 4);

    float p1 = wd.x * a1.x + wd.y * a1.y + wd.z * a1.z + wd.w * a1.w;
    float p2 = wd.x * a2.x + wd.y * a2.y + wd.z * a2.z + wd.w * a2.w;
    float p3 = m1.x * s1.x + m1.y * s1.y + m1.z * s1.z + m1.w * s1.w;
    float p4 = m2.x * s2.x + m2.y * s2.y + m2.z * s2.z + m2.w * s2.w;

#pragma unroll
    for (int o = 16; o > 0; o >>= 1) {
        p1 += __shfl_xor_sync(0xffffffffu, p1, o);
        p2 += __shfl_xor_sync(0xffffffffu, p2, o);
        p3 += __shfl_xor_sync(0xffffffffu, p3, o);
        p4 += __shfl_xor_sync(0xffffffffu, p4, o);
    }
    if (lane == 0) {
        sD1[warp] = p1;
        sD2[warp] = p2;
        sS1[warp] = p3;
        sS2[warp] = p4;
    }
}

// ---------------- per-edge-type pipeline ------------------------------------
__global__ void zero_cnt_kernel(int* __restrict__ cnt, int n)
{
    int i = blockIdx.x * blockDim.x + threadIdx.x;
    if (i < n) cnt[i] = 0;
}

// Bucket edges by destination: store (src, e) per dst slot. Only int atomics.
__global__ void scatter_kernel(const int* __restrict__ src,
                               const int* __restrict__ dst,
                               const float* __restrict__ ssrc,
                               const float* __restrict__ sdst,
                               int* __restrict__ cnt,
                               int* __restrict__ bsrc,
                               float* __restrict__ be)
{
    int i = blockIdx.x * blockDim.x + threadIdx.x;
    if (i >= NE) return;
    int s = src[i];
    int d = dst[i];
    float e = __ldg(&ssrc[s]) + __ldg(&sdst[d]);
    e = e > 0.f ? e : SLOPE * e;
    int pos = atomicAdd(&cnt[d], 1);
    if (pos < CAP) {
        bsrc[d * CAP + pos] = s;
        be[d * CAP + pos]   = e;
    }
}

// One warp per destination node: softmax over its in-edges, weighted gather of
// 128-dim messages. No float atomics; single coalesced 512B write per node.
__global__ void gather_kernel(const float* __restrict__ Whm,
                              const int* __restrict__ cnt,
                              const int* __restrict__ bsrc,
                              const float* __restrict__ be,
                              float* __restrict__ recv, int n)
{
    int warp = (blockIdx.x * blockDim.x + threadIdx.x) >> 5;
    int lane = threadIdx.x & 31;
    if (warp >= n) return;

    int c = cnt[warp];
    if (c > CAP) c = CAP;
    const float* bep = be + (long)warp * CAP;
    const int*   bsp = bsrc + (long)warp * CAP;

    float m = -3.0e38f;
    for (int j = lane; j < c; j += 32) m = fmaxf(m, bep[j]);
#pragma unroll
    for (int o = 16; o > 0; o >>= 1)
        m = fmaxf(m, __shfl_xor_sync(0xffffffffu, m, o));

    float dsum = 0.f;
    for (int j = lane; j < c; j += 32) dsum += __expf(bep[j] - m);
#pragma unroll
    for (int o = 16; o > 0; o >>= 1)
        dsum += __shfl_xor_sync(0xffffffffu, dsum, o);

    float inv = (c > 0) ? 1.f / dsum : 0.f;

    float4 acc = make_float4(0.f, 0.f, 0.f, 0.f);
    for (int j = 0; j < c; j++) {
        float w = __expf(bep[j] - m);          // broadcast loads
        int   s = bsp[j];
        float4 v = *(const float4*)(Whm + (long)s * DOUT + lane * 4);
        acc.x += w * v.x;
        acc.y += w * v.y;
        acc.z += w * v.z;
        acc.w += w * v.w;
    }
    acc.x *= inv; acc.y *= inv; acc.z *= inv; acc.w *= inv;
    *(float4*)(recv + (long)warp * DOUT + lane * 4) = acc;
}

// ---------------- final combine: relu(Wh + recv1 + recv2) -------------------
__global__ void combine_kernel(const float* __restrict__ Wh,
                               const float* __restrict__ r1,
                               const float* __restrict__ r2,
                               float* __restrict__ out, int n4)
{
    int t = blockIdx.x * blockDim.x + threadIdx.x;
    if (t >= n4) return;
    float4 v  = ((const float4*)Wh)[t];
    float4 x1 = ((const float4*)r1)[t];
    float4 x2 = ((const float4*)r2)[t];
    v.x = fmaxf(v.x + x1.x + x2.x, 0.f);
    v.y = fmaxf(v.y + x1.y + x2.y, 0.f);
    v.z = fmaxf(v.z + x1.z + x2.z, 0.f);
    v.w = fmaxf(v.w + x1.w + x2.w, 0.f);
    ((float4*)out)[t] = v;
}

// ---------------- launch --------------------------------------------------
static void* sym_addr(const void* sym)
{
    void* p = nullptr;
    cudaGetSymbolAddress(&p, sym);
    return p;
}

extern "C" void kernel_launch(void* const* d_in, const int* in_sizes, int n_in,
                              void* d_out, int out_size)
{
    const float* feat_P  = (const float*)d_in[0];
    const float* feat_A  = (const float*)d_in[1];
    const int*   p2p_src = (const int*)d_in[2];
    const int*   p2p_dst = (const int*)d_in[3];
    const int*   p2a_src = (const int*)d_in[4];
    const int*   p2a_dst = (const int*)d_in[5];
    const int*   a2p_src = (const int*)d_in[6];
    const int*   a2p_dst = (const int*)d_in[7];
    const int*   a2a_src = (const int*)d_in[8];
    const int*   a2a_dst = (const int*)d_in[9];
    const float* W_P   = (const float*)d_in[10];
    const float* b_P   = (const float*)d_in[11];
    const float* W_A   = (const float*)d_in[12];
    const float* b_A   = (const float*)d_in[13];
    const float* W_p2p = (const float*)d_in[14];
    const float* b_p2p = (const float*)d_in[15];
    const float* W_p2a = (const float*)d_in[16];
    const float* b_p2a = (const float*)d_in[17];
    const float* W_a2p = (const float*)d_in[18];
    const float* b_a2p = (const float*)d_in[19];
    const float* W_a2a = (const float*)d_in[20];
    const float* b_a2a = (const float*)d_in[21];
    const float* a_p2p = (const float*)d_in[22];
    const float* a_p2a = (const float*)d_in[23];
    const float* a_a2p = (const float*)d_in[24];
    const float* a_a2a = (const float*)d_in[25];

    float* Wh_P   = (float*)sym_addr(g_Wh_P);
    float* Wh_A   = (float*)sym_addr(g_Wh_A);
    float* Wh_p2p = (float*)sym_addr(g_Wh_p2p);
    float* Wh_p2a = (float*)sym_addr(g_Wh_p2a);
    float* Wh_a2p = (float*)sym_addr(g_Wh_a2p);
    float* Wh_a2a = (float*)sym_addr(g_Wh_a2a);
    float* recv_p2p = (float*)sym_addr(g_recv_p2p);
    float* recv_a2p = (float*)sym_addr(g_recv_a2p);
    float* recv_p2a = (float*)sym_addr(g_recv_p2a);
    float* recv_a2a = (float*)sym_addr(g_recv_a2a);
    float* s_p2p_src = (float*)sym_addr(g_s_p2p_src);
    float* s_p2p_dst = (float*)sym_addr(g_s_p2p_dst);
    float* s_p2a_src = (float*)sym_addr(g_s_p2a_src);
    float* s_p2a_dst = (float*)sym_addr(g_s_p2a_dst);
    float* s_a2p_src = (float*)sym_addr(g_s_a2p_src);
    float* s_a2p_dst = (float*)sym_addr(g_s_a2p_dst);
    float* s_a2a_src = (float*)sym_addr(g_s_a2a_src);
    float* s_a2a_dst = (float*)sym_addr(g_s_a2a_dst);
    int*   bsrc = (int*)sym_addr(g_bsrc);
    float* be   = (float*)sym_addr(g_be);
    int*   cnt  = (int*)sym_addr(g_cnt);

    float* out = (float*)d_out;

    // 1) fused GEMMs (feat read once per family)
    gemm3_kernel<<<(NP + BM - 1) / BM, 256>>>(feat_P, NP,
        W_P, W_p2p, W_p2a, b_P, b_p2p, b_p2a, Wh_P, Wh_p2p, Wh_p2a);
    gemm3_kernel<<<(NA + BM - 1) / BM, 256>>>(feat_A, NA,
        W_A, W_a2p, W_a2a, b_A, b_a2p, b_a2a, Wh_A, Wh_a2p, Wh_a2a);

    // 2) attention score scalars (warp per node)
    int sgrid = (NP * 32 + 255) / 256;
    s_kernel<<<sgrid, 256>>>(Wh_P, Wh_p2p, Wh_p2a,
                             a_p2p + DOUT, a_a2p + DOUT, a_p2p, a_p2a,
                             s_p2p_dst, s_a2p_dst, s_p2p_src, s_p2a_src, NP);
    s_kernel<<<sgrid, 256>>>(Wh_A, Wh_a2p, Wh_a2a,
                             a_p2a + DOUT, a_a2a + DOUT, a_a2p, a_a2a,
                             s_p2a_dst, s_a2a_dst, s_a2p_src, s_a2a_src, NA);

    // 3) per edge type: bucket by dst, then warp-per-dst softmax gather
    struct Job {
        const int *es, *ed;
        const float *ss, *sd, *whm;
        float* recv;
        int ndst;
    } jobs[4] = {
        {p2p_src, p2p_dst, s_p2p_src, s_p2p_dst, Wh_p2p, recv_p2p, NP},
        {a2p_src, a2p_dst, s_a2p_src, s_a2p_dst, Wh_a2p, recv_a2p, NP},
        {p2a_src, p2a_dst, s_p2a_src, s_p2a_dst, Wh_p2a, recv_p2a, NA},
        {a2a_src, a2a_dst, s_a2a_src, s_a2a_dst, Wh_a2a, recv_a2a, NA},
    };
    for (int t = 0; t < 4; t++) {
        zero_cnt_kernel<<<(jobs[t].ndst + 255) / 256, 256>>>(cnt, jobs[t].ndst);
        scatter_kernel<<<(NE + 255) / 256, 256>>>(jobs[t].es, jobs[t].ed,
                                                  jobs[t].ss, jobs[t].sd,
                                                  cnt, bsrc, be);
        gather_kernel<<<(jobs[t].ndst * 32 + 255) / 256, 256>>>(
            jobs[t].whm, cnt, bsrc, be, jobs[t].recv, jobs[t].ndst);
    }

    // 4) combine + ReLU, write h_P then h_A
    combine_kernel<<<(NP * 32 + 255) / 256, 256>>>(Wh_P, recv_p2p, recv_a2p,
                                                   out, NP * 32);
    combine_kernel<<<(NA * 32 + 255) / 256, 256>>>(Wh_A, recv_p2a, recv_a2a,
                                                   out + (long)NP * DOUT,
                                                   NA * 32);
}

// round 5
// speedup vs baseline: 2.2889x; 2.2889x over previous
#include <cuda_runtime.h>
#include <cuda_bf16.h>
#include <cstdint>
#include <stdint.h>
#include <math.h>

#define NP 100000
#define NA 100000
#define DIN 256
#define DOUT 128
#define NE 1600000
#define SLOPE 0.2f
#define CAP 96

// ---------------- scratch (static device globals; allocation-free) ----------
__device__ __align__(16) float g_Wh_P[NP * DOUT];
__device__ __align__(16) float g_Wh_A[NA * DOUT];
__device__ __align__(16) float g_Wh_p2p[NP * DOUT];
__device__ __align__(16) float g_Wh_p2a[NP * DOUT];
__device__ __align__(16) float g_Wh_a2p[NA * DOUT];
__device__ __align__(16) float g_Wh_a2a[NA * DOUT];
__device__ __align__(16) float g_recv_p2p[NP * DOUT];
__device__ __align__(16) float g_recv_a2p[NP * DOUT];
__device__ __align__(16) float g_recv_p2a[NA * DOUT];
__device__ __align__(16) float g_recv_a2a[NA * DOUT];
__device__ float g_s_p2p_src[NP];
__device__ float g_s_p2p_dst[NP];
__device__ float g_s_p2a_src[NP];
__device__ float g_s_p2a_dst[NA];
__device__ float g_s_a2p_src[NA];
__device__ float g_s_a2p_dst[NP];
__device__ float g_s_a2a_src[NA];
__device__ float g_s_a2a_dst[NA];
__device__ __align__(16) int2  g_bkt[NP * CAP];
__device__ int   g_cnt[NP];
// transposed/split weights: [6 matrices][128 N][256 K] bf16
__device__ __align__(16) __nv_bfloat16 g_Bhi[6 * 128 * 256];
__device__ __align__(16) __nv_bfloat16 g_Blo[6 * 128 * 256];

// ---------------- PTX helpers (baseline sm_103, NO 'a' features) ------------
__device__ __forceinline__ uint32_t smem_u32(const void* p) {
    uint32_t a;
    asm("{ .reg .u64 t; cvta.to.shared.u64 t, %1; cvt.u32.u64 %0, t; }"
        : "=r"(a) : "l"(p));
    return a;
}
__device__ __forceinline__ void ldsm_x4(uint32_t a[4], uint32_t addr) {
    asm volatile("ldmatrix.sync.aligned.m8n8.x4.shared.b16 {%0,%1,%2,%3}, [%4];"
                 : "=r"(a[0]), "=r"(a[1]), "=r"(a[2]), "=r"(a[3]) : "r"(addr));
}
__device__ __forceinline__ void ldsm_x2(uint32_t a[2], uint32_t addr) {
    asm volatile("ldmatrix.sync.aligned.m8n8.x2.shared.b16 {%0,%1}, [%2];"
                 : "=r"(a[0]), "=r"(a[1]) : "r"(addr));
}
__device__ __forceinline__ void mma_bf16(float c[4], const uint32_t a[4],
                                         const uint32_t b[2]) {
    asm volatile(
        "mma.sync.aligned.m16n8k16.row.col.f32.bf16.bf16.f32 "
        "{%0,%1,%2,%3}, {%4,%5,%6,%7}, {%8,%9}, {%0,%1,%2,%3};"
        : "+f"(c[0]), "+f"(c[1]), "+f"(c[2]), "+f"(c[3])
        : "r"(a[0]), "r"(a[1]), "r"(a[2]), "r"(a[3]), "r"(b[0]), "r"(b[1]));
}

// ---------------- weight prep: W[k][n] -> B[w][n][k] hi/lo bf16 -------------
__global__ void prep_w_kernel(const float* __restrict__ W0, const float* __restrict__ W1,
                              const float* __restrict__ W2, const float* __restrict__ W3,
                              const float* __restrict__ W4, const float* __restrict__ W5,
                              __nv_bfloat16* __restrict__ bhi,
                              __nv_bfloat16* __restrict__ blo)
{
    int i = blockIdx.x * blockDim.x + threadIdx.x;
    if (i >= 6 * 128 * 256) return;
    int w = i >> 15;
    int rem = i & 32767;
    int nrow = rem >> 8;
    int k = rem & 255;
    const float* W = (w == 0) ? W0 : (w == 1) ? W1 : (w == 2) ? W2
                   : (w == 3) ? W3 : (w == 4) ? W4 : W5;
    float v = W[k * 128 + nrow];
    __nv_bfloat16 h = __float2bfloat16(v);
    __nv_bfloat16 l = __float2bfloat16(v - __bfloat162float(h));
    bhi[i] = h;
    blo[i] = l;
}

// ---------------- HMMA GEMM: C[n x 128] = feat @ W_w, bf16 3-way split ------
// CTA: 256 thr (8 warps), tile M=128 x N=128, K-chunks of 64.
// smem rows padded to 72 bf16 (144B) -> conflict-free ldmatrix.
#define ASTR 72
#define KCH 64
#define SM_AHI 0
#define SM_ALO 18432
#define SM_BHI 36864
#define SM_BLO 55296
#define GEMM_SMEM 73728

__device__ __forceinline__ void split1(float x, __nv_bfloat16& h, __nv_bfloat16& l) {
    h = __float2bfloat16(x);
    l = __float2bfloat16(x - __bfloat162float(h));
}

__global__ __launch_bounds__(256, 2)
void gemm_mma_kernel(const float* __restrict__ feat, int n,
                     const __nv_bfloat16* __restrict__ Bhi,
                     const __nv_bfloat16* __restrict__ Blo,
                     const float* __restrict__ b0, const float* __restrict__ b1,
                     const float* __restrict__ b2,
                     float* __restrict__ o0, float* __restrict__ o1,
                     float* __restrict__ o2)
{
    extern __shared__ __align__(16) char smem[];
    const uint32_t sbase = smem_u32(smem);

    const int w    = blockIdx.x;           // which weight matrix (0..2)
    const int row0 = blockIdx.y * 128;
    const int tid  = threadIdx.x;
    const int warp = tid >> 5;
    const int lane = tid & 31;

    const __nv_bfloat16* Bh = Bhi + (size_t)w * 128 * 256;
    const __nv_bfloat16* Bl = Blo + (size_t)w * 128 * 256;

    const int m_base = (warp >> 2) * 64;   // 0 or 64
    const int n_base = (warp & 3) * 32;    // 0,32,64,96

    float c[4][4][4];
#pragma unroll
    for (int mt = 0; mt < 4; mt++)
#pragma unroll
        for (int nt = 0; nt < 4; nt++)
#pragma unroll
            for (int r = 0; r < 4; r++) c[mt][nt][r] = 0.f;

    // per-lane ldmatrix base offsets (bytes)
    uint32_t aRow[4], bRow[4];
#pragma unroll
    for (int mt = 0; mt < 4; mt++) {
        int r = m_base + mt * 16 + (lane & 15);
        aRow[mt] = (uint32_t)(r * ASTR * 2) + (((uint32_t)lane >> 4) << 4);
    }
#pragma unroll
    for (int nt = 0; nt < 4; nt++) {
        int r = n_base + nt * 8 + (lane & 7);
        bRow[nt] = (uint32_t)(r * ASTR * 2) + ((((uint32_t)lane >> 3) & 1) << 4);
    }

    for (int kc = 0; kc < DIN; kc += KCH) {
        // ---- fill A: 128 rows x 64 k fp32 -> hi/lo bf16 ----
#pragma unroll
        for (int it = 0; it < 8; it++) {
            int idx = it * 256 + tid;        // 2048 float4s
            int r   = idx >> 4;
            int c4  = idx & 15;
            float4 v = make_float4(0.f, 0.f, 0.f, 0.f);
            if (row0 + r < n)
                v = *(const float4*)(feat + (size_t)(row0 + r) * DIN + kc + c4 * 4);
            __nv_bfloat16 h0, l0, h1, l1, h2, l2, h3, l3;
            split1(v.x, h0, l0); split1(v.y, h1, l1);
            split1(v.z, h2, l2); split1(v.w, h3, l3);
            __nv_bfloat162 hA = __halves2bfloat162(h0, h1);
            __nv_bfloat162 hB = __halves2bfloat162(h2, h3);
            __nv_bfloat162 lA = __halves2bfloat162(l0, l1);
            __nv_bfloat162 lB = __halves2bfloat162(l2, l3);
            uint32_t off = (uint32_t)((r * ASTR + c4 * 4) * 2);
            *(uint2*)(smem + SM_AHI + off) =
                make_uint2(*(uint32_t*)&hA, *(uint32_t*)&hB);
            *(uint2*)(smem + SM_ALO + off) =
                make_uint2(*(uint32_t*)&lA, *(uint32_t*)&lB);
        }
        // ---- fill B: 128 n x 64 k bf16 hi & lo ----
#pragma unroll
        for (int it = 0; it < 4; it++) {
            int idx = it * 256 + tid;        // 1024 int4s per precision
            int nr  = idx >> 3;
            int c16 = idx & 7;
            uint32_t off = (uint32_t)((nr * ASTR + c16 * 8) * 2);
            *(int4*)(smem + SM_BHI + off) =
                *(const int4*)(Bh + (size_t)nr * DIN + kc + c16 * 8);
            *(int4*)(smem + SM_BLO + off) =
                *(const int4*)(Bl + (size_t)nr * DIN + kc + c16 * 8);
        }
        __syncthreads();

#pragma unroll
        for (int ks = 0; ks < 4; ks++) {
            const uint32_t kofs = (uint32_t)(ks * 32);
            uint32_t bh[4][2], bl[4][2];
#pragma unroll
            for (int nt = 0; nt < 4; nt++) {
                ldsm_x2(bh[nt], sbase + SM_BHI + bRow[nt] + kofs);
                ldsm_x2(bl[nt], sbase + SM_BLO + bRow[nt] + kofs);
            }
#pragma unroll
            for (int mt = 0; mt < 4; mt++) {
                uint32_t ah[4], al[4];
                ldsm_x4(ah, sbase + SM_AHI + aRow[mt] + kofs);
                ldsm_x4(al, sbase + SM_ALO + aRow[mt] + kofs);
#pragma unroll
                for (int nt = 0; nt < 4; nt++) {
                    mma_bf16(c[mt][nt], ah, bh[nt]);   // hi*hi
                    mma_bf16(c[mt][nt], al, bh[nt]);   // lo*hi
                    mma_bf16(c[mt][nt], ah, bl[nt]);   // hi*lo
                }
            }
        }
        __syncthreads();
    }

    // ---- epilogue: bias + store ----
    const float* bw = (w == 0) ? b0 : (w == 1) ? b1 : b2;
    float*       ow = (w == 0) ? o0 : (w == 1) ? o1 : o2;
    const int lr = lane >> 2;
    const int lc = (lane & 3) * 2;
    float2 bv[4];
#pragma unroll
    for (int nt = 0; nt < 4; nt++)
        bv[nt] = *(const float2*)(bw + n_base + nt * 8 + lc);

#pragma unroll
    for (int mt = 0; mt < 4; mt++) {
        int r1 = row0 + m_base + mt * 16 + lr;
        int r2 = r1 + 8;
#pragma unroll
        for (int nt = 0; nt < 4; nt++) {
            int col = n_base + nt * 8 + lc;
            if (r1 < n)
                *(float2*)(ow + (size_t)r1 * DOUT + col) =
                    make_float2(c[mt][nt][0] + bv[nt].x, c[mt][nt][1] + bv[nt].y);
            if (r2 < n)
                *(float2*)(ow + (size_t)r2 * DOUT + col) =
                    make_float2(c[mt][nt][2] + bv[nt].x, c[mt][nt][3] + bv[nt].y);
        }
    }
}

// ---------------- attention score dots: s = Wh . a_half ---------------------
__global__ void s_kernel(const float* __restrict__ WhD,
                         const float* __restrict__ Wm1,
                         const float* __restrict__ Wm2,
                         const float* __restrict__ aD1,
                         const float* __restrict__ aD2,
                         const float* __restrict__ aS1,
                         const float* __restrict__ aS2,
                         float* __restrict__ sD1, float* __restrict__ sD2,
                         float* __restrict__ sS1, float* __restrict__ sS2,
                         int n)
{
    int warp = (blockIdx.x * blockDim.x + threadIdx.x) >> 5;
    int lane = threadIdx.x & 31;
    if (warp >= n) return;

    float4 a1 = *(const float4*)(aD1 + lane * 4);
    float4 a2 = *(const float4*)(aD2 + lane * 4);
    float4 s1 = *(const float4*)(aS1 + lane * 4);
    float4 s2 = *(const float4*)(aS2 + lane * 4);

    float4 wd = *(const float4*)(WhD + (size_t)warp * DOUT + lane * 4);
    float4 m1 = *(const float4*)(Wm1 + (size_t)warp * DOUT + lane * 4);
    float4 m2 = *(const float4*)(Wm2 + (size_t)warp * DOUT + lane * 4);

    float p1 = wd.x * a1.x + wd.y * a1.y + wd.z * a1.z + wd.w * a1.w;
    float p2 = wd.x * a2.x + wd.y * a2.y + wd.z * a2.z + wd.w * a2.w;
    float p3 = m1.x * s1.x + m1.y * s1.y + m1.z * s1.z + m1.w * s1.w;
    float p4 = m2.x * s2.x + m2.y * s2.y + m2.z * s2.z + m2.w * s2.w;

#pragma unroll
    for (int o = 16; o > 0; o >>= 1) {
        p1 += __shfl_xor_sync(0xffffffffu, p1, o);
        p2 += __shfl_xor_sync(0xffffffffu, p2, o);
        p3 += __shfl_xor_sync(0xffffffffu, p3, o);
        p4 += __shfl_xor_sync(0xffffffffu, p4, o);
    }
    if (lane == 0) {
        sD1[warp] = p1;
        sD2[warp] = p2;
        sS1[warp] = p3;
        sS2[warp] = p4;
    }
}

// ---------------- per-edge-type pipeline ------------------------------------
__global__ void zero_cnt_kernel(int* __restrict__ cnt, int n)
{
    int i = blockIdx.x * blockDim.x + threadIdx.x;
    if (i < n) cnt[i] = 0;
}

__global__ void scatter_kernel(const int* __restrict__ src,
                               const int* __restrict__ dst,
                               const float* __restrict__ ssrc,
                               const float* __restrict__ sdst,
                               int* __restrict__ cnt,
                               int2* __restrict__ bkt)
{
    int i = blockIdx.x * blockDim.x + threadIdx.x;
    if (i >= NE) return;
    int s = src[i];
    int d = dst[i];
    float e = __ldg(&ssrc[s]) + __ldg(&sdst[d]);
    e = e > 0.f ? e : SLOPE * e;
    int pos = atomicAdd(&cnt[d], 1);
    if (pos < CAP) bkt[d * CAP + pos] = make_int2(s, __float_as_int(e));
}

__global__ void gather_kernel(const float* __restrict__ Whm,
                              const int* __restrict__ cnt,
                              const int2* __restrict__ bkt,
                              float* __restrict__ recv, int n)
{
    int warp = (blockIdx.x * blockDim.x + threadIdx.x) >> 5;
    int lane = threadIdx.x & 31;
    if (warp >= n) return;

    int c = cnt[warp];
    if (c > CAP) c = CAP;
    const int2* bp = bkt + (size_t)warp * CAP;

    float m = -3.0e38f;
    for (int j = lane; j < c; j += 32) m = fmaxf(m, __int_as_float(bp[j].y));
#pragma unroll
    for (int o = 16; o > 0; o >>= 1)
        m = fmaxf(m, __shfl_xor_sync(0xffffffffu, m, o));

    float dsum = 0.f;
    for (int j = lane; j < c; j += 32) dsum += __expf(__int_as_float(bp[j].y) - m);
#pragma unroll
    for (int o = 16; o > 0; o >>= 1)
        dsum += __shfl_xor_sync(0xffffffffu, dsum, o);

    float inv = (c > 0) ? 1.f / dsum : 0.f;

    float4 acc = make_float4(0.f, 0.f, 0.f, 0.f);
    for (int j = 0; j < c; j++) {
        int2 b = bp[j];                     // broadcast
        float w = __expf(__int_as_float(b.y) - m);
        float4 v = *(const float4*)(Whm + (size_t)b.x * DOUT + lane * 4);
        acc.x += w * v.x;
        acc.y += w * v.y;
        acc.z += w * v.z;
        acc.w += w * v.w;
    }
    acc.x *= inv; acc.y *= inv; acc.z *= inv; acc.w *= inv;
    *(float4*)(recv + (size_t)warp * DOUT + lane * 4) = acc;
}

// ---------------- final combine: relu(Wh + recv1 + recv2) -------------------
__global__ void combine_kernel(const float* __restrict__ Wh,
                               const float* __restrict__ r1,
                               const float* __restrict__ r2,
                               float* __restrict__ out, int n4)
{
    int t = blockIdx.x * blockDim.x + threadIdx.x;
    if (t >= n4) return;
    float4 v  = ((const float4*)Wh)[t];
    float4 x1 = ((const float4*)r1)[t];
    float4 x2 = ((const float4*)r2)[t];
    v.x = fmaxf(v.x + x1.x + x2.x, 0.f);
    v.y = fmaxf(v.y + x1.y + x2.y, 0.f);
    v.z = fmaxf(v.z + x1.z + x2.z, 0.f);
    v.w = fmaxf(v.w + x1.w + x2.w, 0.f);
    ((float4*)out)[t] = v;
}

// ---------------- launch ----------------------------------------------------
static void* sym_addr(const void* sym)
{
    void* p = nullptr;
    cudaGetSymbolAddress(&p, sym);
    return p;
}

extern "C" void kernel_launch(void* const* d_in, const int* in_sizes, int n_in,
                              void* d_out, int out_size)
{
    const float* feat_P  = (const float*)d_in[0];
    const float* feat_A  = (const float*)d_in[1];
    const int*   p2p_src = (const int*)d_in[2];
    const int*   p2p_dst = (const int*)d_in[3];
    const int*   p2a_src = (const int*)d_in[4];
    const int*   p2a_dst = (const int*)d_in[5];
    const int*   a2p_src = (const int*)d_in[6];
    const int*   a2p_dst = (const int*)d_in[7];
    const int*   a2a_src = (const int*)d_in[8];
    const int*   a2a_dst = (const int*)d_in[9];
    const float* W_P   = (const float*)d_in[10];
    const float* b_P   = (const float*)d_in[11];
    const float* W_A   = (const float*)d_in[12];
    const float* b_A   = (const float*)d_in[13];
    const float* W_p2p = (const float*)d_in[14];
    const float* b_p2p = (const float*)d_in[15];
    const float* W_p2a = (const float*)d_in[16];
    const float* b_p2a = (const float*)d_in[17];
    const float* W_a2p = (const float*)d_in[18];
    const float* b_a2p = (const float*)d_in[19];
    const float* W_a2a = (const float*)d_in[20];
    const float* b_a2a = (const float*)d_in[21];
    const float* a_p2p = (const float*)d_in[22];
    const float* a_p2a = (const float*)d_in[23];
    const float* a_a2p = (const float*)d_in[24];
    const float* a_a2a = (const float*)d_in[25];

    float* Wh_P   = (float*)sym_addr(g_Wh_P);
    float* Wh_A   = (float*)sym_addr(g_Wh_A);
    float* Wh_p2p = (float*)sym_addr(g_Wh_p2p);
    float* Wh_p2a = (float*)sym_addr(g_Wh_p2a);
    float* Wh_a2p = (float*)sym_addr(g_Wh_a2p);
    float* Wh_a2a = (float*)sym_addr(g_Wh_a2a);
    float* recv_p2p = (float*)sym_addr(g_recv_p2p);
    float* recv_a2p = (float*)sym_addr(g_recv_a2p);
    float* recv_p2a = (float*)sym_addr(g_recv_p2a);
    float* recv_a2a = (float*)sym_addr(g_recv_a2a);
    float* s_p2p_src = (float*)sym_addr(g_s_p2p_src);
    float* s_p2p_dst = (float*)sym_addr(g_s_p2p_dst);
    float* s_p2a_src = (float*)sym_addr(g_s_p2a_src);
    float* s_p2a_dst = (float*)sym_addr(g_s_p2a_dst);
    float* s_a2p_src = (float*)sym_addr(g_s_a2p_src);
    float* s_a2p_dst = (float*)sym_addr(g_s_a2p_dst);
    float* s_a2a_src = (float*)sym_addr(g_s_a2a_src);
    float* s_a2a_dst = (float*)sym_addr(g_s_a2a_dst);
    int2* bkt = (int2*)sym_addr(g_bkt);
    int*  cnt = (int*)sym_addr(g_cnt);
    __nv_bfloat16* Bhi = (__nv_bfloat16*)sym_addr(g_Bhi);
    __nv_bfloat16* Blo = (__nv_bfloat16*)sym_addr(g_Blo);

    float* out = (float*)d_out;

    // 0) weight transpose + bf16 split
    prep_w_kernel<<<(6 * 128 * 256 + 255) / 256, 256>>>(
        W_P, W_p2p, W_p2a, W_A, W_a2p, W_a2a, Bhi, Blo);

    // 1) HMMA GEMMs (3 weight matrices per family; blockIdx.x = w)
    cudaFuncSetAttribute(gemm_mma_kernel,
                         cudaFuncAttributeMaxDynamicSharedMemorySize, GEMM_SMEM);
    {
        dim3 gridP(3, (NP + 127) / 128);
        gemm_mma_kernel<<<gridP, 256, GEMM_SMEM>>>(
            feat_P, NP, Bhi, Blo, b_P, b_p2p, b_p2a, Wh_P, Wh_p2p, Wh_p2a);
        dim3 gridA(3, (NA + 127) / 128);
        gemm_mma_kernel<<<gridA, 256, GEMM_SMEM>>>(
            feat_A, NA, Bhi + 3 * 128 * 256, Blo + 3 * 128 * 256,
            b_A, b_a2p, b_a2a, Wh_A, Wh_a2p, Wh_a2a);
    }

    // 2) attention score scalars (warp per node)
    int sgrid = (NP * 32 + 255) / 256;
    s_kernel<<<sgrid, 256>>>(Wh_P, Wh_p2p, Wh_p2a,
                             a_p2p + DOUT, a_a2p + DOUT, a_p2p, a_p2a,
                             s_p2p_dst, s_a2p_dst, s_p2p_src, s_p2a_src, NP);
    s_kernel<<<sgrid, 256>>>(Wh_A, Wh_a2p, Wh_a2a,
                             a_p2a + DOUT, a_a2a + DOUT, a_a2p, a_a2a,
                             s_p2a_dst, s_a2a_dst, s_a2p_src, s_a2a_src, NA);

    // 3) per edge type: bucket by dst, then warp-per-dst softmax gather
    struct Job {
        const int *es, *ed;
        const float *ss, *sd, *whm;
        float* recv;
        int ndst;
    } jobs[4] = {
        {p2p_src, p2p_dst, s_p2p_src, s_p2p_dst, Wh_p2p, recv_p2p, NP},
        {a2p_src, a2p_dst, s_a2p_src, s_a2p_dst, Wh_a2p, recv_a2p, NP},
        {p2a_src, p2a_dst, s_p2a_src, s_p2a_dst, Wh_p2a, recv_p2a, NA},
        {a2a_src, a2a_dst, s_a2a_src, s_a2a_dst, Wh_a2a, recv_a2a, NA},
    };
    for (int t = 0; t < 4; t++) {
        zero_cnt_kernel<<<(jobs[t].ndst + 255) / 256, 256>>>(cnt, jobs[t].ndst);
        scatter_kernel<<<(NE + 255) / 256, 256>>>(jobs[t].es, jobs[t].ed,
                                                  jobs[t].ss, jobs[t].sd,
                                                  cnt, bkt);
        gather_kernel<<<(jobs[t].ndst * 32 + 255) / 256, 256>>>(
            jobs[t].whm, cnt, bkt, jobs[t].recv, jobs[t].ndst);
    }

    // 4) combine + ReLU
    combine_kernel<<<(NP * 32 + 255) / 256, 256>>>(Wh_P, recv_p2p, recv_a2p,
                                                   out, NP * 32);
    combine_kernel<<<(NA * 32 + 255) / 256, 256>>>(Wh_A, recv_p2a, recv_a2a,
                                                   out + (size_t)NP * DOUT,
                                                   NA * 32);
}

// round 6
// speedup vs baseline: 2.5711x; 1.1233x over previous
#include <cuda_runtime.h>
#include <cuda_bf16.h>
#include <cuda_fp16.h>
#include <cstdint>
#include <stdint.h>
#include <math.h>

#define NP 100000
#define NA 100000
#define DIN 256
#define DOUT 128
#define NE 1600000
#define SLOPE 0.2f
#define CAP 96

// ---------------- scratch (static device globals; allocation-free) ----------
__device__ __align__(16) float g_Wh_P[NP * DOUT];
__device__ __align__(16) float g_Wh_A[NA * DOUT];
__device__ __align__(16) __half g_m_p2p[NP * DOUT];
__device__ __align__(16) __half g_m_p2a[NP * DOUT];
__device__ __align__(16) __half g_m_a2p[NA * DOUT];
__device__ __align__(16) __half g_m_a2a[NA * DOUT];
__device__ __align__(16) float g_recv_p2p[NP * DOUT];
__device__ __align__(16) float g_recv_a2p[NP * DOUT];
__device__ __align__(16) float g_recv_p2a[NA * DOUT];
__device__ __align__(16) float g_recv_a2a[NA * DOUT];
__device__ float g_s_p2p_src[NP];
__device__ float g_s_p2p_dst[NP];
__device__ float g_s_p2a_src[NP];
__device__ float g_s_p2a_dst[NA];
__device__ float g_s_a2p_src[NA];
__device__ float g_s_a2p_dst[NP];
__device__ float g_s_a2a_src[NA];
__device__ float g_s_a2a_dst[NA];
__device__ __align__(16) int2  g_bkt[4][NP * CAP];
__device__ int   g_cnt[4][NP];
// transposed/split weights: [6 matrices][128 N][256 K] bf16
__device__ __align__(16) __nv_bfloat16 g_Bhi[6 * 128 * 256];
__device__ __align__(16) __nv_bfloat16 g_Blo[6 * 128 * 256];

// ---------------- PTX helpers (baseline sm_103, NO 'a' features) ------------
__device__ __forceinline__ uint32_t smem_u32(const void* p) {
    uint32_t a;
    asm("{ .reg .u64 t; cvta.to.shared.u64 t, %1; cvt.u32.u64 %0, t; }"
        : "=r"(a) : "l"(p));
    return a;
}
__device__ __forceinline__ void ldsm_x4(uint32_t a[4], uint32_t addr) {
    asm volatile("ldmatrix.sync.aligned.m8n8.x4.shared.b16 {%0,%1,%2,%3}, [%4];"
                 : "=r"(a[0]), "=r"(a[1]), "=r"(a[2]), "=r"(a[3]) : "r"(addr));
}
__device__ __forceinline__ void ldsm_x2(uint32_t a[2], uint32_t addr) {
    asm volatile("ldmatrix.sync.aligned.m8n8.x2.shared.b16 {%0,%1}, [%2];"
                 : "=r"(a[0]), "=r"(a[1]) : "r"(addr));
}
__device__ __forceinline__ void mma_bf16(float c[4], const uint32_t a[4],
                                         const uint32_t b[2]) {
    asm volatile(
        "mma.sync.aligned.m16n8k16.row.col.f32.bf16.bf16.f32 "
        "{%0,%1,%2,%3}, {%4,%5,%6,%7}, {%8,%9}, {%0,%1,%2,%3};"
        : "+f"(c[0]), "+f"(c[1]), "+f"(c[2]), "+f"(c[3])
        : "r"(a[0]), "r"(a[1]), "r"(a[2]), "r"(a[3]), "r"(b[0]), "r"(b[1]));
}

// ---------------- weight prep: W[k][n] -> B[w][n][k] hi/lo bf16 -------------
__global__ void prep_w_kernel(const float* __restrict__ W0, const float* __restrict__ W1,
                              const float* __restrict__ W2, const float* __restrict__ W3,
                              const float* __restrict__ W4, const float* __restrict__ W5,
                              __nv_bfloat16* __restrict__ bhi,
                              __nv_bfloat16* __restrict__ blo)
{
    int i = blockIdx.x * blockDim.x + threadIdx.x;
    if (i >= 6 * 128 * 256) return;
    int w = i >> 15;
    int rem = i & 32767;
    int nrow = rem >> 8;
    int k = rem & 255;
    const float* W = (w == 0) ? W0 : (w == 1) ? W1 : (w == 2) ? W2
                   : (w == 3) ? W3 : (w == 4) ? W4 : W5;
    float v = W[k * 128 + nrow];
    __nv_bfloat16 h = __float2bfloat16(v);
    __nv_bfloat16 l = __float2bfloat16(v - __bfloat162float(h));
    bhi[i] = h;
    blo[i] = l;
}

// ---------------- HMMA GEMM with fused bias + s-dots + fp16 msg stores ------
// CTA: 256 thr (8 warps), tile M=128 x N=128, K-chunks of 64.
// blockIdx.x = w (0: dst Wh fp32 + 2 s-dots; 1/2: msg fp16 + 1 s-dot).
#define ASTR 72
#define KCH 64
#define SM_AHI 0
#define SM_ALO 18432
#define SM_BHI 36864
#define SM_BLO 55296
#define GEMM_SMEM 73728

__device__ __forceinline__ void split1(float x, __nv_bfloat16& h, __nv_bfloat16& l) {
    h = __float2bfloat16(x);
    l = __float2bfloat16(x - __bfloat162float(h));
}

__global__ __launch_bounds__(256, 2)
void gemm_mma_kernel(const float* __restrict__ feat, int n,
                     const __nv_bfloat16* __restrict__ Bhi,
                     const __nv_bfloat16* __restrict__ Blo,
                     const float* __restrict__ b0, const float* __restrict__ b1,
                     const float* __restrict__ b2,
                     const float* __restrict__ aD1, const float* __restrict__ aD2,
                     const float* __restrict__ aS1, const float* __restrict__ aS2,
                     float* __restrict__ o0,
                     __half* __restrict__ o1h, __half* __restrict__ o2h,
                     float* __restrict__ sD1, float* __restrict__ sD2,
                     float* __restrict__ sS1, float* __restrict__ sS2)
{
    extern __shared__ __align__(16) char smem[];
    __shared__ float sacc[2][128];
    const uint32_t sbase = smem_u32(smem);

    const int w    = blockIdx.x;           // which weight matrix (0..2)
    const int row0 = blockIdx.y * 128;
    const int tid  = threadIdx.x;
    const int warp = tid >> 5;
    const int lane = tid & 31;

    const __nv_bfloat16* Bh = Bhi + (size_t)w * 128 * 256;
    const __nv_bfloat16* Bl = Blo + (size_t)w * 128 * 256;

    const int m_base = (warp >> 2) * 64;   // 0 or 64
    const int n_base = (warp & 3) * 32;    // 0,32,64,96

    float c[4][4][4];
#pragma unroll
    for (int mt = 0; mt < 4; mt++)
#pragma unroll
        for (int nt = 0; nt < 4; nt++)
#pragma unroll
            for (int r = 0; r < 4; r++) c[mt][nt][r] = 0.f;

    // per-lane ldmatrix base offsets (bytes)
    uint32_t aRow[4], bRow[4];
#pragma unroll
    for (int mt = 0; mt < 4; mt++) {
        int r = m_base + mt * 16 + (lane & 15);
        aRow[mt] = (uint32_t)(r * ASTR * 2) + (((uint32_t)lane >> 4) << 4);
    }
#pragma unroll
    for (int nt = 0; nt < 4; nt++) {
        int r = n_base + nt * 8 + (lane & 7);
        bRow[nt] = (uint32_t)(r * ASTR * 2) + ((((uint32_t)lane >> 3) & 1) << 4);
    }

    // zero s-dot accumulators
    if (tid < 256) sacc[tid >> 7][tid & 127] = 0.f;

    for (int kc = 0; kc < DIN; kc += KCH) {
        // ---- fill A: 128 rows x 64 k fp32 -> hi/lo bf16 ----
#pragma unroll
        for (int it = 0; it < 8; it++) {
            int idx = it * 256 + tid;        // 2048 float4s
            int r   = idx >> 4;
            int c4  = idx & 15;
            float4 v = make_float4(0.f, 0.f, 0.f, 0.f);
            if (row0 + r < n)
                v = *(const float4*)(feat + (size_t)(row0 + r) * DIN + kc + c4 * 4);
            __nv_bfloat16 h0, l0, h1, l1, h2, l2, h3, l3;
            split1(v.x, h0, l0); split1(v.y, h1, l1);
            split1(v.z, h2, l2); split1(v.w, h3, l3);
            __nv_bfloat162 hA = __halves2bfloat162(h0, h1);
            __nv_bfloat162 hB = __halves2bfloat162(h2, h3);
            __nv_bfloat162 lA = __halves2bfloat162(l0, l1);
            __nv_bfloat162 lB = __halves2bfloat162(l2, l3);
            uint32_t off = (uint32_t)((r * ASTR + c4 * 4) * 2);
            *(uint2*)(smem + SM_AHI + off) =
                make_uint2(*(uint32_t*)&hA, *(uint32_t*)&hB);
            *(uint2*)(smem + SM_ALO + off) =
                make_uint2(*(uint32_t*)&lA, *(uint32_t*)&lB);
        }
        // ---- fill B: 128 n x 64 k bf16 hi & lo ----
#pragma unroll
        for (int it = 0; it < 4; it++) {
            int idx = it * 256 + tid;        // 1024 int4s per precision
            int nr  = idx >> 3;
            int c16 = idx & 7;
            uint32_t off = (uint32_t)((nr * ASTR + c16 * 8) * 2);
            *(int4*)(smem + SM_BHI + off) =
                *(const int4*)(Bh + (size_t)nr * DIN + kc + c16 * 8);
            *(int4*)(smem + SM_BLO + off) =
                *(const int4*)(Bl + (size_t)nr * DIN + kc + c16 * 8);
        }
        __syncthreads();

#pragma unroll
        for (int ks = 0; ks < 4; ks++) {
            const uint32_t kofs = (uint32_t)(ks * 32);
            uint32_t bh[4][2], bl[4][2];
#pragma unroll
            for (int nt = 0; nt < 4; nt++) {
                ldsm_x2(bh[nt], sbase + SM_BHI + bRow[nt] + kofs);
                ldsm_x2(bl[nt], sbase + SM_BLO + bRow[nt] + kofs);
            }
#pragma unroll
            for (int mt = 0; mt < 4; mt++) {
                uint32_t ah[4], al[4];
                ldsm_x4(ah, sbase + SM_AHI + aRow[mt] + kofs);
                ldsm_x4(al, sbase + SM_ALO + aRow[mt] + kofs);
#pragma unroll
                for (int nt = 0; nt < 4; nt++) {
                    mma_bf16(c[mt][nt], ah, bh[nt]);   // hi*hi
                    mma_bf16(c[mt][nt], al, bh[nt]);   // lo*hi
                    mma_bf16(c[mt][nt], ah, bl[nt]);   // hi*lo
                }
            }
        }
        __syncthreads();
    }

    // ---- epilogue: bias + store (fp32 or fp16) + fused s-dots ----
    const float* bw = (w == 0) ? b0 : (w == 1) ? b1 : b2;
    const float* aq1 = (w == 0) ? aD1 : (w == 1) ? aS1 : aS2;
    const int lr = lane >> 2;
    const int lc = (lane & 3) * 2;
    float2 bv[4], a1v[4], a2v[4];
#pragma unroll
    for (int nt = 0; nt < 4; nt++) {
        int col = n_base + nt * 8 + lc;
        bv[nt]  = *(const float2*)(bw + col);
        a1v[nt] = *(const float2*)(aq1 + col);
        a2v[nt] = (w == 0) ? *(const float2*)(aD2 + col) : make_float2(0.f, 0.f);
    }

#pragma unroll
    for (int mt = 0; mt < 4; mt++) {
        int r1 = row0 + m_base + mt * 16 + lr;
        int r2 = r1 + 8;
        float pa1 = 0.f, pa2 = 0.f, pb1 = 0.f, pb2 = 0.f;
#pragma unroll
        for (int nt = 0; nt < 4; nt++) {
            int col = n_base + nt * 8 + lc;
            float v0 = c[mt][nt][0] + bv[nt].x;
            float v1 = c[mt][nt][1] + bv[nt].y;
            float v2 = c[mt][nt][2] + bv[nt].x;
            float v3 = c[mt][nt][3] + bv[nt].y;
            if (w == 0) {
                if (r1 < n) *(float2*)(o0 + (size_t)r1 * DOUT + col) = make_float2(v0, v1);
                if (r2 < n) *(float2*)(o0 + (size_t)r2 * DOUT + col) = make_float2(v2, v3);
            } else {
                __half* oh = (w == 1) ? o1h : o2h;
                if (r1 < n) *(__half2*)(oh + (size_t)r1 * DOUT + col) = __floats2half2_rn(v0, v1);
                if (r2 < n) *(__half2*)(oh + (size_t)r2 * DOUT + col) = __floats2half2_rn(v2, v3);
            }
            pa1 += v0 * a1v[nt].x + v1 * a1v[nt].y;
            pa2 += v2 * a1v[nt].x + v3 * a1v[nt].y;
            if (w == 0) {
                pb1 += v0 * a2v[nt].x + v1 * a2v[nt].y;
                pb2 += v2 * a2v[nt].x + v3 * a2v[nt].y;
            }
        }
        // reduce across the 4 lanes holding the same row (lane bits 0-1)
        pa1 += __shfl_xor_sync(0xffffffffu, pa1, 1);
        pa1 += __shfl_xor_sync(0xffffffffu, pa1, 2);
        pa2 += __shfl_xor_sync(0xffffffffu, pa2, 1);
        pa2 += __shfl_xor_sync(0xffffffffu, pa2, 2);
        pb1 += __shfl_xor_sync(0xffffffffu, pb1, 1);
        pb1 += __shfl_xor_sync(0xffffffffu, pb1, 2);
        pb2 += __shfl_xor_sync(0xffffffffu, pb2, 1);
        pb2 += __shfl_xor_sync(0xffffffffu, pb2, 2);
        if ((lane & 3) == 0) {
            int lrow = m_base + mt * 16 + lr;
            atomicAdd(&sacc[0][lrow], pa1);
            atomicAdd(&sacc[0][lrow + 8], pa2);
            if (w == 0) {
                atomicAdd(&sacc[1][lrow], pb1);
                atomicAdd(&sacc[1][lrow + 8], pb2);
            }
        }
    }
    __syncthreads();
    if (tid < 128 && row0 + tid < n) {
        if (w == 0) {
            sD1[row0 + tid] = sacc[0][tid];
            sD2[row0 + tid] = sacc[1][tid];
        } else if (w == 1) {
            sS1[row0 + tid] = sacc[0][tid];
        } else {
            sS2[row0 + tid] = sacc[0][tid];
        }
    }
}

// ---------------- fused edge pipeline (4 types, NP==NA==100000) -------------
struct EdgeParams {
    const int*   src[4];
    const int*   dst[4];
    const float* ssrc[4];
    const float* sdst[4];
    const __half* msg[4];
    float*       recv[4];
    int2*        bkt[4];
    int*         cnt[4];
};

__global__ void zero_cnt_kernel(int* __restrict__ cnt)   // cnt = &g_cnt[0][0]
{
    int i = blockIdx.x * blockDim.x + threadIdx.x;
    if (i < 4 * NP) cnt[i] = 0;
}

__global__ void scatter4_kernel(EdgeParams P)
{
    const int t = blockIdx.y;
    int i = blockIdx.x * blockDim.x + threadIdx.x;
    if (i >= NE) return;
    int s = P.src[t][i];
    int d = P.dst[t][i];
    float e = __ldg(&P.ssrc[t][s]) + __ldg(&P.sdst[t][d]);
    e = e > 0.f ? e : SLOPE * e;
    int pos = atomicAdd(&P.cnt[t][d], 1);
    if (pos < CAP) P.bkt[t][(size_t)d * CAP + pos] = make_int2(s, __float_as_int(e));
}

__global__ void gather4_kernel(EdgeParams P)
{
    const int t = blockIdx.y;
    int node = (blockIdx.x * blockDim.x + threadIdx.x) >> 5;
    int lane = threadIdx.x & 31;
    if (node >= NP) return;

    int c = P.cnt[t][node];
    if (c > CAP) c = CAP;
    const int2* bp = P.bkt[t] + (size_t)node * CAP;
    const __half* Whm = P.msg[t];

    float m = -3.0e38f;
    for (int j = lane; j < c; j += 32) m = fmaxf(m, __int_as_float(bp[j].y));
#pragma unroll
    for (int o = 16; o > 0; o >>= 1)
        m = fmaxf(m, __shfl_xor_sync(0xffffffffu, m, o));

    float dsum = 0.f;
    for (int j = lane; j < c; j += 32) dsum += __expf(__int_as_float(bp[j].y) - m);
#pragma unroll
    for (int o = 16; o > 0; o >>= 1)
        dsum += __shfl_xor_sync(0xffffffffu, dsum, o);

    float inv = (c > 0) ? 1.f / dsum : 0.f;

    float4 acc = make_float4(0.f, 0.f, 0.f, 0.f);
    for (int j = 0; j < c; j++) {
        int2 b = bp[j];                     // broadcast
        float w = __expf(__int_as_float(b.y) - m);
        uint2 raw = *(const uint2*)(Whm + (size_t)b.x * DOUT + lane * 4);
        float2 f01 = __half22float2(*(__half2*)&raw.x);
        float2 f23 = __half22float2(*(__half2*)&raw.y);
        acc.x += w * f01.x;
        acc.y += w * f01.y;
        acc.z += w * f23.x;
        acc.w += w * f23.y;
    }
    acc.x *= inv; acc.y *= inv; acc.z *= inv; acc.w *= inv;
    *(float4*)(P.recv[t] + (size_t)node * DOUT + lane * 4) = acc;
}

// ---------------- final combine: relu(Wh + recv1 + recv2) -------------------
__global__ void combine_kernel(const float* __restrict__ Wh,
                               const float* __restrict__ r1,
                               const float* __restrict__ r2,
                               float* __restrict__ out, int n4)
{
    int t = blockIdx.x * blockDim.x + threadIdx.x;
    if (t >= n4) return;
    float4 v  = ((const float4*)Wh)[t];
    float4 x1 = ((const float4*)r1)[t];
    float4 x2 = ((const float4*)r2)[t];
    v.x = fmaxf(v.x + x1.x + x2.x, 0.f);
    v.y = fmaxf(v.y + x1.y + x2.y, 0.f);
    v.z = fmaxf(v.z + x1.z + x2.z, 0.f);
    v.w = fmaxf(v.w + x1.w + x2.w, 0.f);
    ((float4*)out)[t] = v;
}

// ---------------- launch ----------------------------------------------------
static void* sym_addr(const void* sym)
{
    void* p = nullptr;
    cudaGetSymbolAddress(&p, sym);
    return p;
}

extern "C" void kernel_launch(void* const* d_in, const int* in_sizes, int n_in,
                              void* d_out, int out_size)
{
    const float* feat_P  = (const float*)d_in[0];
    const float* feat_A  = (const float*)d_in[1];
    const int*   p2p_src = (const int*)d_in[2];
    const int*   p2p_dst = (const int*)d_in[3];
    const int*   p2a_src = (const int*)d_in[4];
    const int*   p2a_dst = (const int*)d_in[5];
    const int*   a2p_src = (const int*)d_in[6];
    const int*   a2p_dst = (const int*)d_in[7];
    const int*   a2a_src = (const int*)d_in[8];
    const int*   a2a_dst = (const int*)d_in[9];
    const float* W_P   = (const float*)d_in[10];
    const float* b_P   = (const float*)d_in[11];
    const float* W_A   = (const float*)d_in[12];
    const float* b_A   = (const float*)d_in[13];
    const float* W_p2p = (const float*)d_in[14];
    const float* b_p2p = (const float*)d_in[15];
    const float* W_p2a = (const float*)d_in[16];
    const float* b_p2a = (const float*)d_in[17];
    const float* W_a2p = (const float*)d_in[18];
    const float* b_a2p = (const float*)d_in[19];
    const float* W_a2a = (const float*)d_in[20];
    const float* b_a2a = (const float*)d_in[21];
    const float* a_p2p = (const float*)d_in[22];
    const float* a_p2a = (const float*)d_in[23];
    const float* a_a2p = (const float*)d_in[24];
    const float* a_a2a = (const float*)d_in[25];

    float* Wh_P  = (float*)sym_addr(g_Wh_P);
    float* Wh_A  = (float*)sym_addr(g_Wh_A);
    __half* m_p2p = (__half*)sym_addr(g_m_p2p);
    __half* m_p2a = (__half*)sym_addr(g_m_p2a);
    __half* m_a2p = (__half*)sym_addr(g_m_a2p);
    __half* m_a2a = (__half*)sym_addr(g_m_a2a);
    float* recv_p2p = (float*)sym_addr(g_recv_p2p);
    float* recv_a2p = (float*)sym_addr(g_recv_a2p);
    float* recv_p2a = (float*)sym_addr(g_recv_p2a);
    float* recv_a2a = (float*)sym_addr(g_recv_a2a);
    float* s_p2p_src = (float*)sym_addr(g_s_p2p_src);
    float* s_p2p_dst = (float*)sym_addr(g_s_p2p_dst);
    float* s_p2a_src = (float*)sym_addr(g_s_p2a_src);
    float* s_p2a_dst = (float*)sym_addr(g_s_p2a_dst);
    float* s_a2p_src = (float*)sym_addr(g_s_a2p_src);
    float* s_a2p_dst = (float*)sym_addr(g_s_a2p_dst);
    float* s_a2a_src = (float*)sym_addr(g_s_a2a_src);
    float* s_a2a_dst = (float*)sym_addr(g_s_a2a_dst);
    int2* bkt = (int2*)sym_addr(g_bkt);
    int*  cnt = (int*)sym_addr(g_cnt);
    __nv_bfloat16* Bhi = (__nv_bfloat16*)sym_addr(g_Bhi);
    __nv_bfloat16* Blo = (__nv_bfloat16*)sym_addr(g_Blo);

    float* out = (float*)d_out;

    // 0) weight transpose + bf16 split
    prep_w_kernel<<<(6 * 128 * 256 + 255) / 256, 256>>>(
        W_P, W_p2p, W_p2a, W_A, W_a2p, W_a2a, Bhi, Blo);

    // 1) HMMA GEMMs with fused bias + s-dots; msg outputs fp16
    cudaFuncSetAttribute(gemm_mma_kernel,
                         cudaFuncAttributeMaxDynamicSharedMemorySize, GEMM_SMEM);
    {
        dim3 gridP(3, (NP + 127) / 128);
        gemm_mma_kernel<<<gridP, 256, GEMM_SMEM>>>(
            feat_P, NP, Bhi, Blo, b_P, b_p2p, b_p2a,
            a_p2p + DOUT, a_a2p + DOUT, a_p2p, a_p2a,
            Wh_P, m_p2p, m_p2a,
            s_p2p_dst, s_a2p_dst, s_p2p_src, s_p2a_src);
        dim3 gridA(3, (NA + 127) / 128);
        gemm_mma_kernel<<<gridA, 256, GEMM_SMEM>>>(
            feat_A, NA, Bhi + 3 * 128 * 256, Blo + 3 * 128 * 256,
            b_A, b_a2p, b_a2a,
            a_p2a + DOUT, a_a2a + DOUT, a_a2p, a_a2a,
            Wh_A, m_a2p, m_a2a,
            s_p2a_dst, s_a2a_dst, s_a2p_src, s_a2a_src);
    }

    // 2) fused edge pipeline: zero, scatter x4, gather x4
    EdgeParams EP;
    EP.src[0] = p2p_src; EP.dst[0] = p2p_dst; EP.ssrc[0] = s_p2p_src; EP.sdst[0] = s_p2p_dst;
    EP.msg[0] = m_p2p;   EP.recv[0] = recv_p2p;
    EP.src[1] = a2p_src; EP.dst[1] = a2p_dst; EP.ssrc[1] = s_a2p_src; EP.sdst[1] = s_a2p_dst;
    EP.msg[1] = m_a2p;   EP.recv[1] = recv_a2p;
    EP.src[2] = p2a_src; EP.dst[2] = p2a_dst; EP.ssrc[2] = s_p2a_src; EP.sdst[2] = s_p2a_dst;
    EP.msg[2] = m_p2a;   EP.recv[2] = recv_p2a;
    EP.src[3] = a2a_src; EP.dst[3] = a2a_dst; EP.ssrc[3] = s_a2a_src; EP.sdst[3] = s_a2a_dst;
    EP.msg[3] = m_a2a;   EP.recv[3] = recv_a2a;
    for (int t = 0; t < 4; t++) {
        EP.bkt[t] = bkt + (size_t)t * NP * CAP;
        EP.cnt[t] = cnt + (size_t)t * NP;
    }

    zero_cnt_kernel<<<(4 * NP + 255) / 256, 256>>>(cnt);
    {
        dim3 gs((NE + 255) / 256, 4);
        scatter4_kernel<<<gs, 256>>>(EP);
        dim3 gg((NP * 32 + 255) / 256, 4);
        gather4_kernel<<<gg, 256>>>(EP);
    }

    // 3) combine + ReLU
    combine_kernel<<<(NP * 32 + 255) / 256, 256>>>(Wh_P, recv_p2p, recv_a2p,
                                                   out, NP * 32);
    combine_kernel<<<(NA * 32 + 255) / 256, 256>>>(Wh_A, recv_p2a, recv_a2a,
                                                   out + (size_t)NP * DOUT,
                                                   NA * 32);
}